// round 2
// baseline (speedup 1.0000x reference)
#include <cuda_runtime.h>
#include <cstdint>

#define B    256
#define T    1024
#define H    256
#define INP  32
#define OUTD 32
#define G3   768
#define NC   128   // persistent CTAs (all resident on 148 SMs)
#define THR  128

// Static device scratch (allocation-free rule)
__device__ float g_obsT[(size_t)T * INP * B];     // [t][i][b]
__device__ float g_Hst[(size_t)(T + 1) * H * B];  // [t][h][b], t=0 stays zero (BSS)
__device__ float g_M[4 * H * H];                  // merged recurrent matrix [g*256+hc][k]
__device__ float g_C[G3 * B];                     // constants t>=1
__device__ float g_C0[G3 * B];                    // constants t==0
__device__ unsigned g_flags[NC];                  // distributed barrier flags

typedef unsigned long long u64;

__device__ __forceinline__ u64 pack2(float x, float y) {
    u64 r; asm("mov.b64 %0,{%1,%2};" : "=l"(r) : "f"(x), "f"(y)); return r;
}
__device__ __forceinline__ void unpack2(u64 v, float& x, float& y) {
    asm("mov.b64 {%0,%1},%2;" : "=f"(x), "=f"(y) : "l"(v));
}
// packed 2x fp32 FMA
__device__ __forceinline__ u64 fma2(u64 a, u64 b, u64 c) {
    u64 d; asm("fma.rn.f32x2 %0,%1,%2,%3;" : "=l"(d) : "l"(a), "l"(b), "l"(c)); return d;
}
__device__ __forceinline__ float sigf(float x) {
    return __fdividef(1.0f, 1.0f + __expf(-x));
}
__device__ __forceinline__ float tanhx(float x) {
    return __fdividef(2.0f, 1.0f + __expf(-2.0f * x)) - 1.0f;
}

// ---------------------------------------------------------------------------
// obs (B,T,INP) -> obsT [t][i][b]
__global__ void k_transpose(const float* __restrict__ obs) {
    int t = blockIdx.x, b = threadIdx.x;
    const float4* src = (const float4*)(obs + (size_t)b * T * INP + (size_t)t * INP);
    float4 v[8];
#pragma unroll
    for (int q = 0; q < 8; q++) v[q] = src[q];
    float* dst = g_obsT + (size_t)t * (INP * B) + b;
#pragma unroll
    for (int q = 0; q < 8; q++) {
        dst[(4 * q + 0) * B] = v[q].x;
        dst[(4 * q + 1) * B] = v[q].y;
        dst[(4 * q + 2) * B] = v[q].z;
        dst[(4 * q + 3) * B] = v[q].w;
    }
}

// ---------------------------------------------------------------------------
// Merged recurrent matrix M (1024 x 256):
//  rows [0,512): W_hh + W_comb (r,z) ; [512,768): W_comb (xn) ; [768,1024): W_hh_n
//  W_comb[j,k] = sum_o W_ih[j, 32+o] * W_out[o, k]
__global__ void k_prep_M(const float* __restrict__ W_ih,
                         const float* __restrict__ W_hh,
                         const float* __restrict__ W_out) {
    int j = blockIdx.x, k = threadIdx.x;
    float v;
    if (j < 768) {
        float comb = 0.f;
#pragma unroll
        for (int o = 0; o < 32; o++)
            comb = fmaf(W_ih[j * 96 + 32 + o], W_out[o * H + k], comb);
        v = (j < 512) ? (W_hh[j * H + k] + comb) : comb;
    } else {
        v = W_hh[(j - 256) * H + k];
    }
    g_M[j * H + k] = v;
}

// ---------------------------------------------------------------------------
__global__ void k_prep_C(const float* __restrict__ z_dyn,
                         const float* __restrict__ init_y,
                         const float* __restrict__ W_ih,
                         const float* __restrict__ b_ih,
                         const float* __restrict__ b_hh,
                         const float* __restrict__ b_out) {
    int j = blockIdx.x, b = threadIdx.x;
    float zp = 0.f, yb = 0.f, iy = 0.f;
#pragma unroll
    for (int i = 0; i < 32; i++)
        zp = fmaf(z_dyn[b * 32 + i], W_ih[j * 96 + 64 + i], zp);
#pragma unroll
    for (int o = 0; o < 32; o++) {
        float wy = W_ih[j * 96 + 32 + o];
        yb = fmaf(b_out[o], wy, yb);
        iy = fmaf(init_y[b * 32 + o], wy, iy);
    }
    float base = b_ih[j] + (j < 512 ? b_hh[j] : 0.f);
    g_C[j * B + b]  = zp + base + yb;
    g_C0[j * B + b] = zp + base + iy;
}

// ---------------------------------------------------------------------------
// Persistent sequential GRU loop.
// CTA c: h-cols [4*(c>>1), +4), batches [(c&1)*128, +128). Thread owns 1 batch,
// 4 h-cols (8 gate outputs) as 8 packed f32x2 accumulators.
__global__ void __launch_bounds__(THR, 1)
k_rnn(const float* __restrict__ W_ih, const float* __restrict__ b_hh) {
    __shared__ __align__(16) u64 m_s[256][8];      // [k][gate*2+pair]  16KB
    __shared__ __align__(16) u64 c_s[6][THR];      // constants t>=1     6KB
    __shared__ __align__(16) u64 c0_s[6][THR];     // constants t==0     6KB
    __shared__ __align__(16) u64 wobs_s[32][6];    // obs weights      1.5KB

    const int tid = threadIdx.x;
    const int cta = blockIdx.x;
    const int g4  = cta >> 1;
    const int bh  = cta & 1;
    const int hcb = g4 * 4;
    const int b   = bh * 128 + tid;

    for (int idx = tid; idx < 2048; idx += THR) {
        int k = idx >> 3, e = idx & 7, g = e >> 1, p = e & 1;
        int r0 = (g * H + hcb + 2 * p) * H + k;
        m_s[k][e] = pack2(g_M[r0], g_M[r0 + H]);
    }
#pragma unroll
    for (int g = 0; g < 3; g++)
#pragma unroll
        for (int p = 0; p < 2; p++) {
            int r = g * H + hcb + 2 * p;
            c_s [g * 2 + p][tid] = pack2(g_C [r * B + b], g_C [(r + 1) * B + b]);
            c0_s[g * 2 + p][tid] = pack2(g_C0[r * B + b], g_C0[(r + 1) * B + b]);
        }
    if (tid < 32) {
#pragma unroll
        for (int g = 0; g < 3; g++)
#pragma unroll
            for (int p = 0; p < 2; p++) {
                int r = g * H + hcb + 2 * p;
                wobs_s[tid][g * 2 + p] = pack2(W_ih[r * 96 + tid], W_ih[(r + 1) * 96 + tid]);
            }
    }
    const u64 bhh0 = pack2(b_hh[2 * H + hcb + 0], b_hh[2 * H + hcb + 1]);
    const u64 bhh1 = pack2(b_hh[2 * H + hcb + 2], b_hh[2 * H + hcb + 3]);
    __syncthreads();

    // launch-relative barrier base (flags persist across graph replays)
    const unsigned base = *(volatile unsigned*)&g_flags[cta];

    float hp[4] = {0.f, 0.f, 0.f, 0.f};

    // obs registers for step t (prefetched one step ahead)
    float ob[4][8];
    {
        const float* op = g_obsT + b;
#pragma unroll
        for (int ii = 0; ii < 4; ii++)
#pragma unroll
            for (int q = 0; q < 8; q++)
                ob[ii][q] = op[(ii * 8 + q) * B];
    }

    for (int t = 0; t < T; t++) {
        const u64* cs = (t == 0) ? &c0_s[0][0] : &c_s[0][0];
        u64 aR0 = cs[0 * THR + tid], aR1 = cs[1 * THR + tid];
        u64 aZ0 = cs[2 * THR + tid], aZ1 = cs[3 * THR + tid];
        u64 aN0 = cs[4 * THR + tid], aN1 = cs[5 * THR + tid];
        u64 aH0 = bhh0, aH1 = bhh1;

        // issue h prefetch for blocks 0..2 (covered by obs compute below)
        const float* hs = g_Hst + (size_t)t * (H * B) + b;
        float hb[4][8];
#pragma unroll
        for (int blk = 0; blk < 3; blk++)
#pragma unroll
            for (int q = 0; q < 8; q++)
                hb[blk][q] = hs[(blk * 8 + q) * B];

        // obs contribution (registers, prefetched last step): 192 fma2
#pragma unroll
        for (int ii = 0; ii < 4; ii++)
#pragma unroll
            for (int q = 0; q < 8; q++) {
                int i = ii * 8 + q;
                u64 ov2 = pack2(ob[ii][q], ob[ii][q]);
                ulonglong2 w01 = *(const ulonglong2*)&wobs_s[i][0];
                ulonglong2 w23 = *(const ulonglong2*)&wobs_s[i][2];
                ulonglong2 w45 = *(const ulonglong2*)&wobs_s[i][4];
                aR0 = fma2(ov2, w01.x, aR0); aR1 = fma2(ov2, w01.y, aR1);
                aZ0 = fma2(ov2, w23.x, aZ0); aZ1 = fma2(ov2, w23.y, aZ1);
                aN0 = fma2(ov2, w45.x, aN0); aN1 = fma2(ov2, w45.y, aN1);
            }

        // prefetch obs for t+1 (lands during the h loop)
        if (t + 1 < T) {
            const float* op = g_obsT + (size_t)(t + 1) * (INP * B) + b;
#pragma unroll
            for (int ii = 0; ii < 4; ii++)
#pragma unroll
                for (int q = 0; q < 8; q++)
                    ob[ii][q] = op[(ii * 8 + q) * B];
        }

        // recurrent GEMM over K=256 in 32 blocks of 8, 4-buffer rotation,
        // prefetch distance ~3 blocks
#pragma unroll 4
        for (int j = 0; j < 32; j++) {
#pragma unroll
            for (int q = 0; q < 8; q++) {
                int k = j * 8 + q;
                u64 h2 = pack2(hb[j & 3][q], hb[j & 3][q]);
                ulonglong2 w01 = *(const ulonglong2*)&m_s[k][0];
                ulonglong2 w23 = *(const ulonglong2*)&m_s[k][2];
                ulonglong2 w45 = *(const ulonglong2*)&m_s[k][4];
                ulonglong2 w67 = *(const ulonglong2*)&m_s[k][6];
                aR0 = fma2(h2, w01.x, aR0); aR1 = fma2(h2, w01.y, aR1);
                aZ0 = fma2(h2, w23.x, aZ0); aZ1 = fma2(h2, w23.y, aZ1);
                aN0 = fma2(h2, w45.x, aN0); aN1 = fma2(h2, w45.y, aN1);
                aH0 = fma2(h2, w67.x, aH0); aH1 = fma2(h2, w67.y, aH1);
            }
            if (j < 29) {
#pragma unroll
                for (int q = 0; q < 8; q++)
                    hb[(j + 3) & 3][q] = hs[((j + 3) * 8 + q) * B];
            }
        }

        // gates
        float xr[4], xz[4], xn[4], hn[4];
        unpack2(aR0, xr[0], xr[1]); unpack2(aR1, xr[2], xr[3]);
        unpack2(aZ0, xz[0], xz[1]); unpack2(aZ1, xz[2], xz[3]);
        unpack2(aN0, xn[0], xn[1]); unpack2(aN1, xn[2], xn[3]);
        unpack2(aH0, hn[0], hn[1]); unpack2(aH1, hn[2], hn[3]);

        float* hd = g_Hst + (size_t)(t + 1) * (H * B);
#pragma unroll
        for (int j2 = 0; j2 < 4; j2++) {
            float r = sigf(xr[j2]);
            float z = sigf(xz[j2]);
            float n = tanhx(fmaf(r, hn[j2], xn[j2]));
            float hv = fmaf(z, hp[j2] - n, n);   // (1-z)*n + z*h
            hp[j2] = hv;
            hd[(hcb + j2) * B + b] = hv;
        }

        // ---- distributed flag barrier ----
        __threadfence();
        __syncthreads();
        const unsigned tgt = base + (unsigned)(t + 1);
        if (tid == 0) *(volatile unsigned*)&g_flags[cta] = tgt;
        while (*(volatile unsigned*)&g_flags[tid] < tgt) { }
        __threadfence();
        __syncthreads();
    }
}

// ---------------------------------------------------------------------------
// y[b,t,:] = h_t @ W_out^T + b_out
__global__ void __launch_bounds__(256)
k_out(const float* __restrict__ W_out, const float* __restrict__ b_out,
      float* __restrict__ out) {
    __shared__ u64 w2[16][H];
    int t = blockIdx.x, b = threadIdx.x;
#pragma unroll
    for (int p = 0; p < 16; p++)
        w2[p][b] = pack2(W_out[(2 * p) * H + b], W_out[(2 * p + 1) * H + b]);
    __syncthreads();

    u64 acc[16];
#pragma unroll
    for (int p = 0; p < 16; p++) acc[p] = pack2(b_out[2 * p], b_out[2 * p + 1]);

    const float* hs = g_Hst + (size_t)(t + 1) * (H * B) + b;
#pragma unroll 4
    for (int h = 0; h < H; h++) {
        float hv = hs[h * B];
        u64 hv2 = pack2(hv, hv);
#pragma unroll
        for (int p = 0; p < 16; p++) acc[p] = fma2(hv2, w2[p][h], acc[p]);
    }
    float* o = out + (size_t)b * (T * OUTD) + (size_t)t * OUTD;
#pragma unroll
    for (int p = 0; p < 16; p++) {
        float x, y; unpack2(acc[p], x, y);
        o[2 * p] = x; o[2 * p + 1] = y;
    }
}

// ---------------------------------------------------------------------------
extern "C" void kernel_launch(void* const* d_in, const int* in_sizes, int n_in,
                              void* d_out, int out_size) {
    const float* init_y = (const float*)d_in[0];
    const float* obs    = (const float*)d_in[1];
    const float* z_dyn  = (const float*)d_in[2];
    const float* W_ih   = (const float*)d_in[3];
    const float* W_hh   = (const float*)d_in[4];
    const float* b_ih   = (const float*)d_in[5];
    const float* b_hh   = (const float*)d_in[6];
    const float* W_out  = (const float*)d_in[7];
    const float* b_out  = (const float*)d_in[8];
    float* out = (float*)d_out;

    k_transpose<<<T, B>>>(obs);
    k_prep_M<<<1024, H>>>(W_ih, W_hh, W_out);
    k_prep_C<<<G3, B>>>(z_dyn, init_y, W_ih, b_ih, b_hh, b_out);
    k_rnn<<<NC, THR>>>(W_ih, b_hh);
    k_out<<<T, B>>>(W_out, b_out, out);
}

// round 3
// speedup vs baseline: 1.4009x; 1.4009x over previous
#include <cuda_runtime.h>
#include <cstdint>

#define B    256
#define T    1024
#define H    256
#define INP  32
#define OUTD 32
#define G3   768
#define NC   128   // persistent CTAs (all resident)
#define THR  256

typedef unsigned long long u64;

// Static device scratch (allocation-free rule)
__device__ float g_obsT[(size_t)T * INP * B];       // [t][i][b]
__device__ float g_Hst[(size_t)(T + 1) * H * B];    // [t][h][b], t=0 stays zero (BSS)
__device__ float g_M[4 * H * H];                    // merged recurrent matrix
__device__ float g_C[G3 * B];                       // constants t>=1
__device__ float g_C0[G3 * B];                      // constants t==0
__device__ u64   g_gobs[(size_t)T * 3 * 128 * B];   // precomputed gate inputs (pairs)
__device__ unsigned g_flags[NC];                    // barrier flags (monotonic)

__device__ __forceinline__ u64 pack2(float x, float y) {
    u64 r; asm("mov.b64 %0,{%1,%2};" : "=l"(r) : "f"(x), "f"(y)); return r;
}
__device__ __forceinline__ void unpack2(u64 v, float& x, float& y) {
    asm("mov.b64 {%0,%1},%2;" : "=f"(x), "=f"(y) : "l"(v));
}
__device__ __forceinline__ u64 fma2(u64 a, u64 b, u64 c) {
    u64 d; asm("fma.rn.f32x2 %0,%1,%2,%3;" : "=l"(d) : "l"(a), "l"(b), "l"(c)); return d;
}
__device__ __forceinline__ float sigf(float x) {
    return __fdividef(1.0f, 1.0f + __expf(-x));
}
__device__ __forceinline__ float tanhx(float x) {
    return __fdividef(2.0f, 1.0f + __expf(-2.0f * x)) - 1.0f;
}

// ---------------------------------------------------------------------------
// obs (B,T,INP) -> obsT [t][i][b]
__global__ void k_transpose(const float* __restrict__ obs) {
    int t = blockIdx.x, b = threadIdx.x;
    const float4* src = (const float4*)(obs + (size_t)b * T * INP + (size_t)t * INP);
    float4 v[8];
#pragma unroll
    for (int q = 0; q < 8; q++) v[q] = src[q];
    float* dst = g_obsT + (size_t)t * (INP * B) + b;
#pragma unroll
    for (int q = 0; q < 8; q++) {
        dst[(4 * q + 0) * B] = v[q].x;
        dst[(4 * q + 1) * B] = v[q].y;
        dst[(4 * q + 2) * B] = v[q].z;
        dst[(4 * q + 3) * B] = v[q].w;
    }
}

// ---------------------------------------------------------------------------
// Merged recurrent matrix M (1024 x 256):
//  rows [0,512): W_hh + W_comb (r,z) ; [512,768): W_comb (xn) ; [768,1024): W_hh_n
//  W_comb[j,k] = sum_o W_ih[j, 32+o] * W_out[o, k]
__global__ void k_prep_M(const float* __restrict__ W_ih,
                         const float* __restrict__ W_hh,
                         const float* __restrict__ W_out) {
    int j = blockIdx.x, k = threadIdx.x;
    float v;
    if (j < 768) {
        float comb = 0.f;
#pragma unroll
        for (int o = 0; o < 32; o++)
            comb = fmaf(W_ih[j * 96 + 32 + o], W_out[o * H + k], comb);
        v = (j < 512) ? (W_hh[j * H + k] + comb) : comb;
    } else {
        v = W_hh[(j - 256) * H + k];
    }
    g_M[j * H + k] = v;
}

// ---------------------------------------------------------------------------
// Per-(gate-row, batch) constants.
__global__ void k_prep_C(const float* __restrict__ z_dyn,
                         const float* __restrict__ init_y,
                         const float* __restrict__ W_ih,
                         const float* __restrict__ b_ih,
                         const float* __restrict__ b_hh,
                         const float* __restrict__ b_out) {
    int j = blockIdx.x, b = threadIdx.x;
    float zp = 0.f, yb = 0.f, iy = 0.f;
#pragma unroll
    for (int i = 0; i < 32; i++)
        zp = fmaf(z_dyn[b * 32 + i], W_ih[j * 96 + 64 + i], zp);
#pragma unroll
    for (int o = 0; o < 32; o++) {
        float wy = W_ih[j * 96 + 32 + o];
        yb = fmaf(b_out[o], wy, yb);
        iy = fmaf(init_y[b * 32 + o], wy, iy);
    }
    float base = b_ih[j] + (j < 512 ? b_hh[j] : 0.f);
    g_C[j * B + b]  = zp + base + yb;
    g_C0[j * B + b] = zp + base + iy;
}

// ---------------------------------------------------------------------------
// Precompute gate-input planes for every step:
// g_gobs[t][g][P][b] = pack2 over the h-col pair (2P, 2P+1) of
//    C(t)[j][b] + sum_i obs_t[i][b] * W_ih[j][i]    (C(0)=C0)
// grid = (T, 384), block = 256
__global__ void __launch_bounds__(256)
k_prep_gobs(const float* __restrict__ W_ih) {
    int t = blockIdx.x;
    int gp = blockIdx.y;            // 0..383
    int g  = gp >> 7;               // gate 0..2
    int P  = gp & 127;              // pair 0..127
    int b  = threadIdx.x;
    int j0 = g * H + 2 * P;

    __shared__ float w0[32], w1[32];
    if (b < 32)       w0[b]      = W_ih[j0 * 96 + b];
    else if (b < 64)  w1[b - 32] = W_ih[(j0 + 1) * 96 + (b - 32)];
    __syncthreads();

    const float* cb = (t == 0) ? g_C0 : g_C;
    float a0 = cb[j0 * B + b];
    float a1 = cb[(j0 + 1) * B + b];
    const float* op = g_obsT + (size_t)t * (INP * B) + b;
#pragma unroll
    for (int i = 0; i < 32; i++) {
        float ov = op[i * B];
        a0 = fmaf(ov, w0[i], a0);
        a1 = fmaf(ov, w1[i], a1);
    }
    g_gobs[(((size_t)t * 3 + g) * 128 + P) * B + b] = pack2(a0, a1);
}

// ---------------------------------------------------------------------------
// Persistent sequential GRU loop.
// CTA c: h-cols [8*(c>>2), +8), batches [(c&3)*64, +64).
// Thread (s = tid>>6, bl = tid&63): batch b = bg*64+bl, h-cols {hcb+2s, hcb+2s+1}.
// 4 packed f32x2 accumulators (r, z, xn, hn) over the pair.
__global__ void __launch_bounds__(THR, 1)
k_rnn(const float* __restrict__ b_hh) {
    __shared__ __align__(16) u64 m_s[256][4][4];   // [k][s][gate] 32KB

    const int tid = threadIdx.x;
    const int cta = blockIdx.x;
    const int g4  = cta >> 2;         // h-group 0..31
    const int bg  = cta & 3;          // batch group 0..3
    const int hcb = g4 * 8;
    const int s   = tid >> 6;         // 0..3 -> pair within group
    const int b   = bg * 64 + (tid & 63);
    const int P   = g4 * 4 + s;       // global pair index 0..127

    // load M slice: m_s[k][s2][g] = pair (hcb+2*s2, +1) of gate-plane g at col k
#pragma unroll
    for (int e = 0; e < 16; e++) {
        int k = tid;                   // coalesced over k
        int s2 = e >> 2, g = e & 3;
        int r0 = (g * H + hcb + 2 * s2) * H + k;
        m_s[k][s2][g] = pack2(g_M[r0], g_M[r0 + H]);
    }
    const u64 bhh2 = pack2(b_hh[2 * H + hcb + 2 * s], b_hh[2 * H + hcb + 2 * s + 1]);
    __syncthreads();

    const unsigned base = *(volatile unsigned*)&g_flags[cta];  // own flag only

    float hp0 = 0.f, hp1 = 0.f;
    const u64* gob = g_gobs + (size_t)P * B + b;
    const size_t gplane = (size_t)128 * B;

    for (int t = 0; t < T; t++) {
        // accumulator init from precomputed planes (3 coalesced LDG.64)
        const u64* gp = gob + (size_t)t * 3 * gplane;
        u64 aR = gp[0];
        u64 aZ = gp[gplane];
        u64 aN = gp[2 * gplane];
        u64 aH = bhh2;

        // software-pipelined h loads (4-buffer rotation, distance 3 blocks)
        const float* hs = g_Hst + (size_t)t * (H * B) + b;
        float hb[4][8];
#pragma unroll
        for (int blk = 0; blk < 3; blk++)
#pragma unroll
            for (int q = 0; q < 8; q++)
                hb[blk][q] = hs[(blk * 8 + q) * B];

#pragma unroll 4
        for (int j = 0; j < 32; j++) {
#pragma unroll
            for (int q = 0; q < 8; q++) {
                int k = j * 8 + q;
                float hv = hb[j & 3][q];
                u64 h2 = pack2(hv, hv);
                ulonglong2 m01 = *(const ulonglong2*)&m_s[k][s][0];
                ulonglong2 m23 = *(const ulonglong2*)&m_s[k][s][2];
                aR = fma2(h2, m01.x, aR);
                aZ = fma2(h2, m01.y, aZ);
                aN = fma2(h2, m23.x, aN);
                aH = fma2(h2, m23.y, aH);
            }
            if (j < 29) {
#pragma unroll
                for (int q = 0; q < 8; q++)
                    hb[(j + 3) & 3][q] = hs[((j + 3) * 8 + q) * B];
            }
        }

        // gates for the 2 owned h-cols
        float xr0, xr1, xz0, xz1, xn0, xn1, hn0, hn1;
        unpack2(aR, xr0, xr1); unpack2(aZ, xz0, xz1);
        unpack2(aN, xn0, xn1); unpack2(aH, hn0, hn1);
        float r0 = sigf(xr0), r1 = sigf(xr1);
        float z0 = sigf(xz0), z1 = sigf(xz1);
        float n0 = tanhx(fmaf(r0, hn0, xn0));
        float n1 = tanhx(fmaf(r1, hn1, xn1));
        float h0 = fmaf(z0, hp0 - n0, n0);
        float h1 = fmaf(z1, hp1 - n1, n1);
        hp0 = h0; hp1 = h1;

        float* hd = g_Hst + (size_t)(t + 1) * (H * B);
        hd[(hcb + 2 * s) * B + b]     = h0;
        hd[(hcb + 2 * s + 1) * B + b] = h1;

        // ---- sub-group barrier: only the 32 CTAs sharing this batch group ----
        __threadfence();
        __syncthreads();
        const unsigned tgt = base + (unsigned)(t + 1);
        if (tid == 0) *(volatile unsigned*)&g_flags[cta] = tgt;
        if (tid < 32) {
            volatile unsigned* f = &g_flags[tid * 4 + bg];
            while ((int)(*f - tgt) < 0) { }
            __threadfence();
        }
        __syncthreads();
    }
}

// ---------------------------------------------------------------------------
// y[b,t,:] = h_t @ W_out^T + b_out
__global__ void __launch_bounds__(256)
k_out(const float* __restrict__ W_out, const float* __restrict__ b_out,
      float* __restrict__ out) {
    __shared__ u64 w2[16][H];
    int t = blockIdx.x, b = threadIdx.x;
#pragma unroll
    for (int p = 0; p < 16; p++)
        w2[p][b] = pack2(W_out[(2 * p) * H + b], W_out[(2 * p + 1) * H + b]);
    __syncthreads();

    u64 acc[16];
#pragma unroll
    for (int p = 0; p < 16; p++) acc[p] = pack2(b_out[2 * p], b_out[2 * p + 1]);

    const float* hs = g_Hst + (size_t)(t + 1) * (H * B) + b;
#pragma unroll 4
    for (int h = 0; h < H; h++) {
        float hv = hs[h * B];
        u64 hv2 = pack2(hv, hv);
#pragma unroll
        for (int p = 0; p < 16; p++) acc[p] = fma2(hv2, w2[p][h], acc[p]);
    }
    float* o = out + (size_t)b * (T * OUTD) + (size_t)t * OUTD;
#pragma unroll
    for (int p = 0; p < 16; p++) {
        float x, y; unpack2(acc[p], x, y);
        o[2 * p] = x; o[2 * p + 1] = y;
    }
}

// ---------------------------------------------------------------------------
extern "C" void kernel_launch(void* const* d_in, const int* in_sizes, int n_in,
                              void* d_out, int out_size) {
    const float* init_y = (const float*)d_in[0];
    const float* obs    = (const float*)d_in[1];
    const float* z_dyn  = (const float*)d_in[2];
    const float* W_ih   = (const float*)d_in[3];
    const float* W_hh   = (const float*)d_in[4];
    const float* b_ih   = (const float*)d_in[5];
    const float* b_hh   = (const float*)d_in[6];
    const float* W_out  = (const float*)d_in[7];
    const float* b_out  = (const float*)d_in[8];
    float* out = (float*)d_out;

    k_transpose<<<T, B>>>(obs);
    k_prep_M<<<1024, H>>>(W_ih, W_hh, W_out);
    k_prep_C<<<G3, B>>>(z_dyn, init_y, W_ih, b_ih, b_hh, b_out);
    k_prep_gobs<<<dim3(T, 384), 256>>>(W_ih);
    k_rnn<<<NC, THR>>>(b_hh);
    k_out<<<T, B>>>(W_out, b_out, out);
}

// round 4
// speedup vs baseline: 1.4847x; 1.0598x over previous
#include <cuda_runtime.h>
#include <cstdint>

#define B    256
#define T    1024
#define H    256
#define INP  32
#define OUTD 32
#define G3   768
#define NC   128   // persistent CTAs (all resident)
#define THR  256

typedef unsigned long long u64;

// Static device scratch (allocation-free rule)
__device__ float g_obsT[(size_t)T * INP * B];       // [t][i][b]
__device__ float g_Hst[(size_t)(T + 1) * H * B];    // [t][h][b], t=0 stays zero (BSS)
__device__ float g_M[4 * H * H];                    // merged recurrent matrix
__device__ float g_C[G3 * B];                       // constants t>=1
__device__ float g_C0[G3 * B];                      // constants t==0
__device__ unsigned g_flags[NC];                    // barrier flags (monotonic)

__device__ __forceinline__ u64 pack2(float x, float y) {
    u64 r; asm("mov.b64 %0,{%1,%2};" : "=l"(r) : "f"(x), "f"(y)); return r;
}
__device__ __forceinline__ void unpack2(u64 v, float& x, float& y) {
    asm("mov.b64 {%0,%1},%2;" : "=f"(x), "=f"(y) : "l"(v));
}
__device__ __forceinline__ u64 fma2(u64 a, u64 b, u64 c) {
    u64 d; asm("fma.rn.f32x2 %0,%1,%2,%3;" : "=l"(d) : "l"(a), "l"(b), "l"(c)); return d;
}
__device__ __forceinline__ float sigf(float x) {
    return __fdividef(1.0f, 1.0f + __expf(-x));
}
__device__ __forceinline__ float tanhx(float x) {
    return __fdividef(2.0f, 1.0f + __expf(-2.0f * x)) - 1.0f;
}
// gpu-scope release store / acquire load (no MEMBAR, no L1 flush)
__device__ __forceinline__ void st_release(unsigned* p, unsigned v) {
    asm volatile("st.global.release.gpu.b32 [%0], %1;" :: "l"(p), "r"(v) : "memory");
}
__device__ __forceinline__ unsigned ld_acquire(const unsigned* p) {
    unsigned v;
    asm volatile("ld.global.acquire.gpu.b32 %0, [%1];" : "=r"(v) : "l"(p) : "memory");
    return v;
}

// ---------------------------------------------------------------------------
// obs (B,T,INP) -> obsT [t][i][b]
__global__ void k_transpose(const float* __restrict__ obs) {
    int t = blockIdx.x, b = threadIdx.x;
    const float4* src = (const float4*)(obs + (size_t)b * T * INP + (size_t)t * INP);
    float4 v[8];
#pragma unroll
    for (int q = 0; q < 8; q++) v[q] = src[q];
    float* dst = g_obsT + (size_t)t * (INP * B) + b;
#pragma unroll
    for (int q = 0; q < 8; q++) {
        dst[(4 * q + 0) * B] = v[q].x;
        dst[(4 * q + 1) * B] = v[q].y;
        dst[(4 * q + 2) * B] = v[q].z;
        dst[(4 * q + 3) * B] = v[q].w;
    }
}

// ---------------------------------------------------------------------------
// Merged recurrent matrix M (1024 x 256):
//  rows [0,512): W_hh + W_comb (r,z) ; [512,768): W_comb (xn) ; [768,1024): W_hh_n
//  W_comb[j,k] = sum_o W_ih[j, 32+o] * W_out[o, k]
__global__ void k_prep_M(const float* __restrict__ W_ih,
                         const float* __restrict__ W_hh,
                         const float* __restrict__ W_out) {
    int j = blockIdx.x, k = threadIdx.x;
    float v;
    if (j < 768) {
        float comb = 0.f;
#pragma unroll
        for (int o = 0; o < 32; o++)
            comb = fmaf(W_ih[j * 96 + 32 + o], W_out[o * H + k], comb);
        v = (j < 512) ? (W_hh[j * H + k] + comb) : comb;
    } else {
        v = W_hh[(j - 256) * H + k];
    }
    g_M[j * H + k] = v;
}

// ---------------------------------------------------------------------------
// Per-(gate-row, batch) constants.
__global__ void k_prep_C(const float* __restrict__ z_dyn,
                         const float* __restrict__ init_y,
                         const float* __restrict__ W_ih,
                         const float* __restrict__ b_ih,
                         const float* __restrict__ b_hh,
                         const float* __restrict__ b_out) {
    int j = blockIdx.x, b = threadIdx.x;
    float zp = 0.f, yb = 0.f, iy = 0.f;
#pragma unroll
    for (int i = 0; i < 32; i++)
        zp = fmaf(z_dyn[b * 32 + i], W_ih[j * 96 + 64 + i], zp);
#pragma unroll
    for (int o = 0; o < 32; o++) {
        float wy = W_ih[j * 96 + 32 + o];
        yb = fmaf(b_out[o], wy, yb);
        iy = fmaf(init_y[b * 32 + o], wy, iy);
    }
    float base = b_ih[j] + (j < 512 ? b_hh[j] : 0.f);
    g_C[j * B + b]  = zp + base + yb;
    g_C0[j * B + b] = zp + base + iy;
}

// ---------------------------------------------------------------------------
// Persistent sequential GRU loop.
// CTA c: h-cols [8*(c>>2), +8), batches [(c&3)*64, +64).
// Thread (s = tid>>6, bl = tid&63): batch b = bg*64+bl, h-col pair {hcb+2s, +1}.
__global__ void __launch_bounds__(THR, 1)
k_rnn(const float* __restrict__ W_ih, const float* __restrict__ b_hh) {
    __shared__ __align__(16) u64 m_s[256][4][4];    // [k][s][gate]      32KB
    __shared__ __align__(16) u64 c_s[3][THR];       // constants t>=1     6KB
    __shared__ __align__(16) u64 c0_s[3][THR];      // constants t==0     6KB
    __shared__ __align__(16) u64 wobs_s[32][4][4];  // [i][s][gate(pad)]  4KB

    const int tid = threadIdx.x;
    const int cta = blockIdx.x;
    const int g4  = cta >> 2;          // h-group 0..31
    const int bg  = cta & 3;           // batch group 0..3
    const int hcb = g4 * 8;
    const int s   = tid >> 6;          // pair index 0..3
    const int b   = bg * 64 + (tid & 63);

    // M slice: m_s[k][s2][g] = pair (hcb+2*s2, +1) of gate-plane g at col k
#pragma unroll
    for (int e = 0; e < 16; e++) {
        int k = tid;
        int s2 = e >> 2, g = e & 3;
        int r0 = (g * H + hcb + 2 * s2) * H + k;
        m_s[k][s2][g] = pack2(g_M[r0], g_M[r0 + H]);
    }
    // constants
#pragma unroll
    for (int g = 0; g < 3; g++) {
        int r = g * H + hcb + 2 * s;
        c_s [g][tid] = pack2(g_C [r * B + b], g_C [(r + 1) * B + b]);
        c0_s[g][tid] = pack2(g_C0[r * B + b], g_C0[(r + 1) * B + b]);
    }
    // obs weights
    if (tid < 32) {
#pragma unroll
        for (int s2 = 0; s2 < 4; s2++)
#pragma unroll
            for (int g = 0; g < 3; g++) {
                int r = (g * H + hcb + 2 * s2) * 96 + tid;
                wobs_s[tid][s2][g] = pack2(W_ih[r], W_ih[r + 96]);
            }
    }
    const u64 bhh2 = pack2(b_hh[2 * H + hcb + 2 * s], b_hh[2 * H + hcb + 2 * s + 1]);
    __syncthreads();

    const unsigned base = ld_acquire(&g_flags[cta]);  // all flags equal at launch

    float hp0 = 0.f, hp1 = 0.f;

    for (int t = 0; t < T; t++) {
        const u64* cs = (t == 0) ? &c0_s[0][0] : &c_s[0][0];
        u64 aR = cs[0 * THR + tid];
        u64 aZ = cs[1 * THR + tid];
        u64 aN = cs[2 * THR + tid];
        u64 aH = bhh2;

        // issue obs loads (L1 path; read-only data) + first h blocks (L2 path)
        const float* op = g_obsT + (size_t)t * (INP * B) + b;
        float ov[32];
#pragma unroll
        for (int i = 0; i < 32; i++) ov[i] = op[i * B];

        const float* hs = g_Hst + (size_t)t * (H * B) + b;
        float hb[4][8];
#pragma unroll
        for (int blk = 0; blk < 3; blk++)
#pragma unroll
            for (int q = 0; q < 8; q++)
                hb[blk][q] = __ldcg(hs + (blk * 8 + q) * B);

        // obs contribution: 96 fma2 (covers the h-load latency)
#pragma unroll
        for (int i = 0; i < 32; i++) {
            u64 o2 = pack2(ov[i], ov[i]);
            ulonglong2 w01 = *(const ulonglong2*)&wobs_s[i][s][0];
            u64 w2v = wobs_s[i][s][2];
            aR = fma2(o2, w01.x, aR);
            aZ = fma2(o2, w01.y, aZ);
            aN = fma2(o2, w2v, aN);
        }

        // recurrent GEMM, 32 blocks of 8, 4-buffer rotation, distance 3
#pragma unroll 4
        for (int j = 0; j < 32; j++) {
#pragma unroll
            for (int q = 0; q < 8; q++) {
                int k = j * 8 + q;
                float hv = hb[j & 3][q];
                u64 h2 = pack2(hv, hv);
                ulonglong2 m01 = *(const ulonglong2*)&m_s[k][s][0];
                ulonglong2 m23 = *(const ulonglong2*)&m_s[k][s][2];
                aR = fma2(h2, m01.x, aR);
                aZ = fma2(h2, m01.y, aZ);
                aN = fma2(h2, m23.x, aN);
                aH = fma2(h2, m23.y, aH);
            }
            if (j < 29) {
#pragma unroll
                for (int q = 0; q < 8; q++)
                    hb[(j + 3) & 3][q] = __ldcg(hs + ((j + 3) * 8 + q) * B);
            }
        }

        // gates
        float xr0, xr1, xz0, xz1, xn0, xn1, hn0, hn1;
        unpack2(aR, xr0, xr1); unpack2(aZ, xz0, xz1);
        unpack2(aN, xn0, xn1); unpack2(aH, hn0, hn1);
        float r0 = sigf(xr0), r1 = sigf(xr1);
        float z0 = sigf(xz0), z1 = sigf(xz1);
        float n0 = tanhx(fmaf(r0, hn0, xn0));
        float n1 = tanhx(fmaf(r1, hn1, xn1));
        float h0 = fmaf(z0, hp0 - n0, n0);
        float h1 = fmaf(z1, hp1 - n1, n1);
        hp0 = h0; hp1 = h1;

        float* hd = g_Hst + (size_t)(t + 1) * (H * B);
        hd[(hcb + 2 * s) * B + b]     = h0;
        hd[(hcb + 2 * s + 1) * B + b] = h1;

        // ---- release/acquire barrier over the 32 CTAs of this batch group ----
        __syncthreads();                       // all stores of this CTA happen-before
        const unsigned tgt = base + (unsigned)(t + 1);
        if (tid == 0) st_release(&g_flags[cta], tgt);
        if (tid < 32) {
            const unsigned* f = &g_flags[(tid << 2) | bg];
            while ((int)(ld_acquire(f) - tgt) < 0) { }
        }
        __syncthreads();
    }
}

// ---------------------------------------------------------------------------
// y[b,t,:] = h_t @ W_out^T + b_out
__global__ void __launch_bounds__(256)
k_out(const float* __restrict__ W_out, const float* __restrict__ b_out,
      float* __restrict__ out) {
    __shared__ u64 w2[16][H];
    int t = blockIdx.x, b = threadIdx.x;
#pragma unroll
    for (int p = 0; p < 16; p++)
        w2[p][b] = pack2(W_out[(2 * p) * H + b], W_out[(2 * p + 1) * H + b]);
    __syncthreads();

    u64 acc[16];
#pragma unroll
    for (int p = 0; p < 16; p++) acc[p] = pack2(b_out[2 * p], b_out[2 * p + 1]);

    const float* hs = g_Hst + (size_t)(t + 1) * (H * B) + b;
#pragma unroll 4
    for (int h = 0; h < H; h++) {
        float hv = hs[h * B];
        u64 hv2 = pack2(hv, hv);
#pragma unroll
        for (int p = 0; p < 16; p++) acc[p] = fma2(hv2, w2[p][h], acc[p]);
    }
    float* o = out + (size_t)b * (T * OUTD) + (size_t)t * OUTD;
#pragma unroll
    for (int p = 0; p < 16; p++) {
        float x, y; unpack2(acc[p], x, y);
        o[2 * p] = x; o[2 * p + 1] = y;
    }
}

// ---------------------------------------------------------------------------
extern "C" void kernel_launch(void* const* d_in, const int* in_sizes, int n_in,
                              void* d_out, int out_size) {
    const float* init_y = (const float*)d_in[0];
    const float* obs    = (const float*)d_in[1];
    const float* z_dyn  = (const float*)d_in[2];
    const float* W_ih   = (const float*)d_in[3];
    const float* W_hh   = (const float*)d_in[4];
    const float* b_ih   = (const float*)d_in[5];
    const float* b_hh   = (const float*)d_in[6];
    const float* W_out  = (const float*)d_in[7];
    const float* b_out  = (const float*)d_in[8];
    float* out = (float*)d_out;

    k_transpose<<<T, B>>>(obs);
    k_prep_M<<<1024, H>>>(W_ih, W_hh, W_out);
    k_prep_C<<<G3, B>>>(z_dyn, init_y, W_ih, b_ih, b_hh, b_out);
    k_rnn<<<NC, THR>>>(W_ih, b_hh);
    k_out<<<T, B>>>(W_out, b_out, out);
}